// round 7
// baseline (speedup 1.0000x reference)
#include <cuda_runtime.h>

#define D_FEAT 64

__device__ int g_row_ptr[100001];

// Kernel A: row_ptr[r] = lower_bound(row, E, r).
__global__ void build_row_ptr(const int* __restrict__ row, int n, int E) {
    int r = blockIdx.x * blockDim.x + threadIdx.x;
    if (r > n) return;
    int lo = 0, hi = E;
    while (lo < hi) {
        int mid = (lo + hi) >> 1;
        if (__ldg(&row[mid]) < r) lo = mid + 1;
        else hi = mid;
    }
    g_row_ptr[r] = lo;
}

// Kernel B: one warp per row, lane owns features {2l,2l+1} (float2).
// 8-edge unrolled main loop (8 gathers in flight). 64-thread blocks: only 2
// warps per block, so a straggler row holds 1 sibling warp's slot instead of 7
// (row-degree variance was capping achieved occupancy at ~79%).
__global__ void __launch_bounds__(64)
spmm_mean_warp_per_row(const float* __restrict__ x,
                       const float* __restrict__ vals,
                       const int* __restrict__ col,
                       float* __restrict__ out,
                       int n) {
    int warp_id = (blockIdx.x * blockDim.x + threadIdx.x) >> 5;
    int lane = threadIdx.x & 31;
    if (warp_id >= n) return;

    int s = g_row_ptr[warp_id];
    int e = g_row_ptr[warp_id + 1];

    const float* xb = x + 2 * lane;
    float2 a0 = make_float2(0.f, 0.f);
    float2 a1 = make_float2(0.f, 0.f);

    int i = s;

    // Main loop: 8 edges; cols issued first so gathers launch ASAP.
    for (; i + 8 <= e; i += 8) {
        int c0 = __ldg(&col[i + 0]);
        int c1 = __ldg(&col[i + 1]);
        int c2 = __ldg(&col[i + 2]);
        int c3 = __ldg(&col[i + 3]);
        int c4 = __ldg(&col[i + 4]);
        int c5 = __ldg(&col[i + 5]);
        int c6 = __ldg(&col[i + 6]);
        int c7 = __ldg(&col[i + 7]);
        float2 x0 = __ldg(reinterpret_cast<const float2*>(xb + (size_t)c0 * D_FEAT));
        float2 x1 = __ldg(reinterpret_cast<const float2*>(xb + (size_t)c1 * D_FEAT));
        float2 x2 = __ldg(reinterpret_cast<const float2*>(xb + (size_t)c2 * D_FEAT));
        float2 x3 = __ldg(reinterpret_cast<const float2*>(xb + (size_t)c3 * D_FEAT));
        float2 x4 = __ldg(reinterpret_cast<const float2*>(xb + (size_t)c4 * D_FEAT));
        float2 x5 = __ldg(reinterpret_cast<const float2*>(xb + (size_t)c5 * D_FEAT));
        float2 x6 = __ldg(reinterpret_cast<const float2*>(xb + (size_t)c6 * D_FEAT));
        float2 x7 = __ldg(reinterpret_cast<const float2*>(xb + (size_t)c7 * D_FEAT));
        float v0 = __ldg(&vals[i + 0]);
        float v1 = __ldg(&vals[i + 1]);
        float v2 = __ldg(&vals[i + 2]);
        float v3 = __ldg(&vals[i + 3]);
        float v4 = __ldg(&vals[i + 4]);
        float v5 = __ldg(&vals[i + 5]);
        float v6 = __ldg(&vals[i + 6]);
        float v7 = __ldg(&vals[i + 7]);
        a0.x = fmaf(v0, x0.x, a0.x); a0.y = fmaf(v0, x0.y, a0.y);
        a1.x = fmaf(v1, x1.x, a1.x); a1.y = fmaf(v1, x1.y, a1.y);
        a0.x = fmaf(v2, x2.x, a0.x); a0.y = fmaf(v2, x2.y, a0.y);
        a1.x = fmaf(v3, x3.x, a1.x); a1.y = fmaf(v3, x3.y, a1.y);
        a0.x = fmaf(v4, x4.x, a0.x); a0.y = fmaf(v4, x4.y, a0.y);
        a1.x = fmaf(v5, x5.x, a1.x); a1.y = fmaf(v5, x5.y, a1.y);
        a0.x = fmaf(v6, x6.x, a0.x); a0.y = fmaf(v6, x6.y, a0.y);
        a1.x = fmaf(v7, x7.x, a1.x); a1.y = fmaf(v7, x7.y, a1.y);
    }

    // Secondary: 4 edges.
    for (; i + 4 <= e; i += 4) {
        int c0 = __ldg(&col[i + 0]);
        int c1 = __ldg(&col[i + 1]);
        int c2 = __ldg(&col[i + 2]);
        int c3 = __ldg(&col[i + 3]);
        float2 x0 = __ldg(reinterpret_cast<const float2*>(xb + (size_t)c0 * D_FEAT));
        float2 x1 = __ldg(reinterpret_cast<const float2*>(xb + (size_t)c1 * D_FEAT));
        float2 x2 = __ldg(reinterpret_cast<const float2*>(xb + (size_t)c2 * D_FEAT));
        float2 x3 = __ldg(reinterpret_cast<const float2*>(xb + (size_t)c3 * D_FEAT));
        float v0 = __ldg(&vals[i + 0]);
        float v1 = __ldg(&vals[i + 1]);
        float v2 = __ldg(&vals[i + 2]);
        float v3 = __ldg(&vals[i + 3]);
        a0.x = fmaf(v0, x0.x, a0.x); a0.y = fmaf(v0, x0.y, a0.y);
        a1.x = fmaf(v1, x1.x, a1.x); a1.y = fmaf(v1, x1.y, a1.y);
        a0.x = fmaf(v2, x2.x, a0.x); a0.y = fmaf(v2, x2.y, a0.y);
        a1.x = fmaf(v3, x3.x, a1.x); a1.y = fmaf(v3, x3.y, a1.y);
    }

    // Tail: <=3 scalar edges.
    for (; i < e; i++) {
        int   c = __ldg(&col[i]);
        float v = __ldg(&vals[i]);
        float2 xv = __ldg(reinterpret_cast<const float2*>(xb + (size_t)c * D_FEAT));
        a0.x = fmaf(v, xv.x, a0.x);
        a0.y = fmaf(v, xv.y, a0.y);
    }

    int deg = e - s;
    float inv = 1.0f / (float)(deg > 0 ? deg : 1);
    float2 o = make_float2((a0.x + a1.x) * inv, (a0.y + a1.y) * inv);

    *reinterpret_cast<float2*>(&out[(size_t)warp_id * D_FEAT + 2 * lane]) = o;
}

extern "C" void kernel_launch(void* const* d_in, const int* in_sizes, int n_in,
                              void* d_out, int out_size) {
    const float* x    = (const float*)d_in[0];
    const float* vals = (const float*)d_in[1];
    const int*   row  = (const int*)d_in[2];
    const int*   col  = (const int*)d_in[3];
    float* out = (float*)d_out;

    int n = in_sizes[0] / D_FEAT;   // 100000
    int E = in_sizes[1];            // 1200000

    {
        int threads = 256;
        int blocks = (n + 1 + threads - 1) / threads;
        build_row_ptr<<<blocks, threads>>>(row, n, E);
    }
    {
        int threads = 64;                    // 2 warps/block: straggler isolation
        int rows_per_block = threads / 32;
        int blocks = (n + rows_per_block - 1) / rows_per_block;
        spmm_mean_warp_per_row<<<blocks, threads>>>(x, vals, col, out, n);
    }
}

// round 8
// speedup vs baseline: 1.2223x; 1.2223x over previous
#include <cuda_runtime.h>

#define D_FEAT 64

__device__ int g_row_ptr[100001];

// Kernel A: boundary scatter. row is sorted, so thread i writes the CSR start
// for every row beginning at edge i (including empty rows between row[i-1]
// and row[i]). Thread E handles the tail rows. Streaming coalesced reads —
// no dependent-load binary search chain.
__global__ void build_row_ptr_scatter(const int* __restrict__ row, int n, int E) {
    int i = blockIdx.x * blockDim.x + threadIdx.x;
    if (i > E) return;
    if (i == 0) {
        int r0 = __ldg(&row[0]);
        for (int r = 0; r <= r0; r++) g_row_ptr[r] = 0;
    } else if (i == E) {
        int rp = __ldg(&row[E - 1]);
        for (int r = rp + 1; r <= n; r++) g_row_ptr[r] = E;
    } else {
        int rc = __ldg(&row[i]);
        int rp = __ldg(&row[i - 1]);
        // usually rc == rp (no write); boundary: write (rp, rc]
        for (int r = rp + 1; r <= rc; r++) g_row_ptr[r] = i;
    }
}

// Kernel B: one warp per row, lane owns features {2l,2l+1} (float2).
// 8-edge unrolled main loop (8 gathers in flight), regs=32 -> 64 warps/SM.
__global__ void __launch_bounds__(128)
spmm_mean_warp_per_row(const float* __restrict__ x,
                       const float* __restrict__ vals,
                       const int* __restrict__ col,
                       float* __restrict__ out,
                       int n) {
    int warp_id = (blockIdx.x * blockDim.x + threadIdx.x) >> 5;
    int lane = threadIdx.x & 31;
    if (warp_id >= n) return;

    int s = g_row_ptr[warp_id];
    int e = g_row_ptr[warp_id + 1];

    const float* xb = x + 2 * lane;
    float2 a0 = make_float2(0.f, 0.f);
    float2 a1 = make_float2(0.f, 0.f);

    int i = s;

    // Main loop: 8 edges; cols issued first so gathers launch ASAP.
    for (; i + 8 <= e; i += 8) {
        int c0 = __ldg(&col[i + 0]);
        int c1 = __ldg(&col[i + 1]);
        int c2 = __ldg(&col[i + 2]);
        int c3 = __ldg(&col[i + 3]);
        int c4 = __ldg(&col[i + 4]);
        int c5 = __ldg(&col[i + 5]);
        int c6 = __ldg(&col[i + 6]);
        int c7 = __ldg(&col[i + 7]);
        float2 x0 = __ldg(reinterpret_cast<const float2*>(xb + (size_t)c0 * D_FEAT));
        float2 x1 = __ldg(reinterpret_cast<const float2*>(xb + (size_t)c1 * D_FEAT));
        float2 x2 = __ldg(reinterpret_cast<const float2*>(xb + (size_t)c2 * D_FEAT));
        float2 x3 = __ldg(reinterpret_cast<const float2*>(xb + (size_t)c3 * D_FEAT));
        float2 x4 = __ldg(reinterpret_cast<const float2*>(xb + (size_t)c4 * D_FEAT));
        float2 x5 = __ldg(reinterpret_cast<const float2*>(xb + (size_t)c5 * D_FEAT));
        float2 x6 = __ldg(reinterpret_cast<const float2*>(xb + (size_t)c6 * D_FEAT));
        float2 x7 = __ldg(reinterpret_cast<const float2*>(xb + (size_t)c7 * D_FEAT));
        float v0 = __ldg(&vals[i + 0]);
        float v1 = __ldg(&vals[i + 1]);
        float v2 = __ldg(&vals[i + 2]);
        float v3 = __ldg(&vals[i + 3]);
        float v4 = __ldg(&vals[i + 4]);
        float v5 = __ldg(&vals[i + 5]);
        float v6 = __ldg(&vals[i + 6]);
        float v7 = __ldg(&vals[i + 7]);
        a0.x = fmaf(v0, x0.x, a0.x); a0.y = fmaf(v0, x0.y, a0.y);
        a1.x = fmaf(v1, x1.x, a1.x); a1.y = fmaf(v1, x1.y, a1.y);
        a0.x = fmaf(v2, x2.x, a0.x); a0.y = fmaf(v2, x2.y, a0.y);
        a1.x = fmaf(v3, x3.x, a1.x); a1.y = fmaf(v3, x3.y, a1.y);
        a0.x = fmaf(v4, x4.x, a0.x); a0.y = fmaf(v4, x4.y, a0.y);
        a1.x = fmaf(v5, x5.x, a1.x); a1.y = fmaf(v5, x5.y, a1.y);
        a0.x = fmaf(v6, x6.x, a0.x); a0.y = fmaf(v6, x6.y, a0.y);
        a1.x = fmaf(v7, x7.x, a1.x); a1.y = fmaf(v7, x7.y, a1.y);
    }

    // Secondary: 4 edges.
    for (; i + 4 <= e; i += 4) {
        int c0 = __ldg(&col[i + 0]);
        int c1 = __ldg(&col[i + 1]);
        int c2 = __ldg(&col[i + 2]);
        int c3 = __ldg(&col[i + 3]);
        float2 x0 = __ldg(reinterpret_cast<const float2*>(xb + (size_t)c0 * D_FEAT));
        float2 x1 = __ldg(reinterpret_cast<const float2*>(xb + (size_t)c1 * D_FEAT));
        float2 x2 = __ldg(reinterpret_cast<const float2*>(xb + (size_t)c2 * D_FEAT));
        float2 x3 = __ldg(reinterpret_cast<const float2*>(xb + (size_t)c3 * D_FEAT));
        float v0 = __ldg(&vals[i + 0]);
        float v1 = __ldg(&vals[i + 1]);
        float v2 = __ldg(&vals[i + 2]);
        float v3 = __ldg(&vals[i + 3]);
        a0.x = fmaf(v0, x0.x, a0.x); a0.y = fmaf(v0, x0.y, a0.y);
        a1.x = fmaf(v1, x1.x, a1.x); a1.y = fmaf(v1, x1.y, a1.y);
        a0.x = fmaf(v2, x2.x, a0.x); a0.y = fmaf(v2, x2.y, a0.y);
        a1.x = fmaf(v3, x3.x, a1.x); a1.y = fmaf(v3, x3.y, a1.y);
    }

    // Tail: <=3 scalar edges.
    for (; i < e; i++) {
        int   c = __ldg(&col[i]);
        float v = __ldg(&vals[i]);
        float2 xv = __ldg(reinterpret_cast<const float2*>(xb + (size_t)c * D_FEAT));
        a0.x = fmaf(v, xv.x, a0.x);
        a0.y = fmaf(v, xv.y, a0.y);
    }

    int deg = e - s;
    float inv = 1.0f / (float)(deg > 0 ? deg : 1);
    float2 o = make_float2((a0.x + a1.x) * inv, (a0.y + a1.y) * inv);

    *reinterpret_cast<float2*>(&out[(size_t)warp_id * D_FEAT + 2 * lane]) = o;
}

extern "C" void kernel_launch(void* const* d_in, const int* in_sizes, int n_in,
                              void* d_out, int out_size) {
    const float* x    = (const float*)d_in[0];
    const float* vals = (const float*)d_in[1];
    const int*   row  = (const int*)d_in[2];
    const int*   col  = (const int*)d_in[3];
    float* out = (float*)d_out;

    int n = in_sizes[0] / D_FEAT;   // 100000
    int E = in_sizes[1];            // 1200000

    {
        int threads = 256;
        int blocks = (E + 1 + threads - 1) / threads;
        build_row_ptr_scatter<<<blocks, threads>>>(row, n, E);
    }
    {
        int threads = 128;                   // 4 warps/block
        int rows_per_block = threads / 32;
        int blocks = (n + rows_per_block - 1) / rows_per_block;
        spmm_mean_warp_per_row<<<blocks, threads>>>(x, vals, col, out, n);
    }
}